// round 2
// baseline (speedup 1.0000x reference)
#include <cuda_runtime.h>
#include <math.h>

// MambaState elementwise update:
//   a      = sigmoid(a_logit)        [D] broadcast over batch
//   delta  = softplus(delta_log)     [D] broadcast over batch
//   new_state = a * prev + delta * (b_t * v_t)
//   y         = c_t * new_state
// Output buffer: [new_state (B*D) | y (B*D)]  (tuple order from reference)
//
// B=8192, D=4096, fp32. Pure HBM-streaming kernel: 512 MiB read + 256 MiB
// write. Implementation: float4 per thread, exact grid (no bounds check:
// N4 == 32768*256 exactly), params cached in L2.

#define BATCH     8192
#define STATE_DIM 4096
#define D4        (STATE_DIM / 4)           // 1024 float4 per row
#define N4        ((BATCH * STATE_DIM) / 4) // 8388608 float4 elements

__device__ __forceinline__ float sigmoidf_(float x) {
    return 1.0f / (1.0f + __expf(-x));
}

__device__ __forceinline__ float softplusf_(float x) {
    // numerically stable softplus
    return fmaxf(x, 0.0f) + log1pf(__expf(-fabsf(x)));
}

__global__ __launch_bounds__(256)
void mamba_state_kernel(const float4* __restrict__ prev,
                        const float4* __restrict__ b_t,
                        const float4* __restrict__ v_t,
                        const float4* __restrict__ c_t,
                        const float4* __restrict__ a_logit,
                        const float4* __restrict__ delta_log,
                        float4* __restrict__ out_state,
                        float4* __restrict__ out_y) {
    int i = blockIdx.x * blockDim.x + threadIdx.x;   // float4 index; grid is exact
    int col = i & (D4 - 1);                          // D4 = 1024, power of two

    // Front-batch the four big streaming loads (MLP), then cached params.
    float4 p = prev[i];
    float4 b = b_t[i];
    float4 v = v_t[i];
    float4 c = c_t[i];
    float4 al = a_logit[col];
    float4 dl = delta_log[col];

    float a0 = sigmoidf_(al.x), a1 = sigmoidf_(al.y),
          a2 = sigmoidf_(al.z), a3 = sigmoidf_(al.w);
    float d0 = softplusf_(dl.x), d1 = softplusf_(dl.y),
          d2 = softplusf_(dl.z), d3 = softplusf_(dl.w);

    float4 ns;
    ns.x = fmaf(a0, p.x, d0 * (b.x * v.x));
    ns.y = fmaf(a1, p.y, d1 * (b.y * v.y));
    ns.z = fmaf(a2, p.z, d2 * (b.z * v.z));
    ns.w = fmaf(a3, p.w, d3 * (b.w * v.w));

    float4 yv;
    yv.x = c.x * ns.x;
    yv.y = c.y * ns.y;
    yv.z = c.z * ns.z;
    yv.w = c.w * ns.w;

    out_state[i] = ns;
    out_y[i]     = yv;
}

extern "C" void kernel_launch(void* const* d_in, const int* in_sizes, int n_in,
                              void* d_out, int out_size) {
    const float4* prev      = (const float4*)d_in[0];
    const float4* b_t       = (const float4*)d_in[1];
    const float4* v_t       = (const float4*)d_in[2];
    const float4* c_t       = (const float4*)d_in[3];
    const float4* a_logit   = (const float4*)d_in[4];
    const float4* delta_log = (const float4*)d_in[5];

    float* out = (float*)d_out;
    float4* out_state = (float4*)out;                         // first B*D floats
    float4* out_y     = (float4*)(out + BATCH * STATE_DIM);   // second B*D floats

    const int threads = 256;
    const int blocks  = N4 / threads;                         // 32768, exact
    mamba_state_kernel<<<blocks, threads>>>(prev, b_t, v_t, c_t,
                                            a_logit, delta_log,
                                            out_state, out_y);
}